// round 13
// baseline (speedup 1.0000x reference)
#include <cuda_runtime.h>
#include <cuda_fp16.h>
#include <stdint.h>
#include <math.h>

#define N_NODES 100000
#define N_EDGES 1600000
#define N_CLS   40

// ---------------- scratch (static device arrays; no cudaMalloc) -------------
__device__ __half g_t[(size_t)N_NODES * 128];   // transform output (x @ W), fp16
__device__ float  g_x[(size_t)N_NODES * 128];   // layer activation buffer, fp32
__device__ int    g_deg[N_NODES];
__device__ float  g_dis[N_NODES];               // (deg+1)^{-1/2}
__device__ int    g_rowptr[N_NODES + 1];
__device__ int    g_cursor[N_NODES];
__device__ int    g_csrc[N_EDGES];              // CSR: src ids grouped by dst

// ---------------- degree histogram ------------------------------------------
__global__ void zero_deg_kernel() {
    int i = blockIdx.x * blockDim.x + threadIdx.x;
    if (i < N_NODES) g_deg[i] = 0;
}

__global__ void hist_deg_kernel(const int* __restrict__ ei) {
    int e = blockIdx.x * blockDim.x + threadIdx.x;
    if (e < N_EDGES) atomicAdd(&g_deg[ei[N_EDGES + e]], 1);
}

// ---------------- single-block scan: rowptr, cursor, dis ---------------------
__global__ __launch_bounds__(1024) void scan_kernel() {
    const int T = 1024;
    int tid = threadIdx.x;
    const int per = (N_NODES + T - 1) / T;          // 98
    int start = tid * per;
    int end   = start + per; if (end > N_NODES) end = N_NODES;
    if (start > N_NODES) start = N_NODES;

    int sum = 0;
    for (int i = start; i < end; i++) sum += g_deg[i];

    __shared__ int s[T];
    s[tid] = sum;
    __syncthreads();
    for (int off = 1; off < T; off <<= 1) {
        int v = 0;
        if (tid >= off) v = s[tid - off];
        __syncthreads();
        if (tid >= off) s[tid] += v;
        __syncthreads();
    }
    int run = s[tid] - sum;     // exclusive prefix

    for (int i = start; i < end; i++) {
        int d = g_deg[i];
        g_rowptr[i] = run;
        g_cursor[i] = run;
        g_dis[i] = rsqrtf((float)(d + 1));
        run += d;
    }
    if (end == N_NODES) g_rowptr[N_NODES] = run;
}

__global__ void csr_fill_kernel(const int* __restrict__ ei) {
    int e = blockIdx.x * blockDim.x + threadIdx.x;
    if (e < N_EDGES) {
        int s = ei[e];
        int d = ei[N_EDGES + e];
        int pos = atomicAdd(&g_cursor[d], 1);
        g_csrc[pos] = s;
    }
}

// ---------------- helpers ----------------------------------------------------
// fp16 hi/lo split: x ~= hi + lo, exact to ~2^-22 relative.
__device__ __forceinline__ void h_split(float x, __half& hi, __half& lo) {
    __half h = __float2half_rn(x);
    hi = h;
    lo = __float2half_rn(x - __half2float(h));
}

__device__ __forceinline__ uint32_t pack_h2(__half a, __half b) {
    __half2 h = __halves2half2(a, b);
    return *(uint32_t*)&h;
}

__device__ __forceinline__ void mma_f16(float* c, uint32_t a0, uint32_t a1,
                                        uint32_t a2, uint32_t a3,
                                        uint32_t b0, uint32_t b1) {
    asm volatile(
        "mma.sync.aligned.m16n8k16.row.col.f32.f16.f16.f32 "
        "{%0,%1,%2,%3}, {%4,%5,%6,%7}, {%8,%9}, {%0,%1,%2,%3};"
        : "+f"(c[0]), "+f"(c[1]), "+f"(c[2]), "+f"(c[3])
        : "r"(a0), "r"(a1), "r"(a2), "r"(a3), "r"(b0), "r"(b1));
}

__device__ __forceinline__ void ldsm_x4(uint32_t& r0, uint32_t& r1,
                                        uint32_t& r2, uint32_t& r3, uint32_t addr) {
    asm volatile("ldmatrix.sync.aligned.m8n8.x4.shared.b16 {%0,%1,%2,%3}, [%4];"
                 : "=r"(r0), "=r"(r1), "=r"(r2), "=r"(r3) : "r"(addr));
}

__device__ __forceinline__ void ldsm_x2t(uint32_t& r0, uint32_t& r1, uint32_t addr) {
    asm volatile("ldmatrix.sync.aligned.m8n8.x2.trans.shared.b16 {%0,%1}, [%2];"
                 : "=r"(r0), "=r"(r1) : "r"(addr));
}

// ---------------- 3-term fp16 tensor-core GEMM (ldmatrix) --------------------
__global__ __launch_bounds__(256, 2) void gemm_f16x3_kernel(
    const float* __restrict__ A, const float* __restrict__ W,
    __half* __restrict__ C, int M, int Ncols)
{
    __shared__ __half Ahs[128][40];
    __shared__ __half Als[128][40];
    __shared__ __half Bhs[32][72];
    __shared__ __half Bls[32][72];

    const int tid  = threadIdx.x;
    const int warp = tid >> 5;
    const int lane = tid & 31;
    const int g    = lane >> 2;
    const int tg   = lane & 3;
    const int wm   = (warp >> 1) * 32;
    const int wn   = (warp & 1) * 32;
    const int rowBase = blockIdx.x * 128;
    const int colBase = blockIdx.y * 64;

    const int li   = lane & 7;
    const int quad = lane >> 3;
    const int aRow = li + (quad & 1) * 8;
    const int aCol = (quad >> 1) * 8;
    const int bRow = ((lane >> 3) & 1) * 8 + li;

    const uint32_t sAh = (uint32_t)__cvta_generic_to_shared(&Ahs[0][0]);
    const uint32_t sAl = (uint32_t)__cvta_generic_to_shared(&Als[0][0]);
    const uint32_t sBh = (uint32_t)__cvta_generic_to_shared(&Bhs[0][0]);
    const uint32_t sBl = (uint32_t)__cvta_generic_to_shared(&Bls[0][0]);

    float acc[2][4][4];
#pragma unroll
    for (int mt = 0; mt < 2; mt++)
#pragma unroll
        for (int nt = 0; nt < 4; nt++)
#pragma unroll
            for (int i = 0; i < 4; i++) acc[mt][nt][i] = 0.f;

    float4 pa[4], pb[2];
#pragma unroll
    for (int i = 0; i < 4; i++) {
        int f = tid + i * 256;
        int r = f >> 3, kq = f & 7;
        int grow = rowBase + r;
        pa[i] = (grow < M) ? *(const float4*)&A[(size_t)grow * 128 + kq * 4]
                           : make_float4(0.f, 0.f, 0.f, 0.f);
    }
#pragma unroll
    for (int i = 0; i < 2; i++) {
        int f = tid + i * 256;
        int k = f >> 4, cq = f & 15;
        int c0 = colBase + cq * 4;
        pb[i] = (c0 < Ncols) ? *(const float4*)&W[(size_t)k * Ncols + c0]
                             : make_float4(0.f, 0.f, 0.f, 0.f);
    }

    for (int kc = 0; kc < 128; kc += 32) {
#pragma unroll
        for (int i = 0; i < 4; i++) {
            int f = tid + i * 256;
            int r = f >> 3, kq = f & 7;
            __half h0, l0, h1, l1, h2, l2, h3, l3;
            h_split(pa[i].x, h0, l0); h_split(pa[i].y, h1, l1);
            h_split(pa[i].z, h2, l2); h_split(pa[i].w, h3, l3);
            *(uint2*)&Ahs[r][kq * 4] = make_uint2(pack_h2(h0, h1), pack_h2(h2, h3));
            *(uint2*)&Als[r][kq * 4] = make_uint2(pack_h2(l0, l1), pack_h2(l2, l3));
        }
#pragma unroll
        for (int i = 0; i < 2; i++) {
            int f = tid + i * 256;
            int k = f >> 4, cq = f & 15;
            __half h0, l0, h1, l1, h2, l2, h3, l3;
            h_split(pb[i].x, h0, l0); h_split(pb[i].y, h1, l1);
            h_split(pb[i].z, h2, l2); h_split(pb[i].w, h3, l3);
            *(uint2*)&Bhs[k][cq * 4] = make_uint2(pack_h2(h0, h1), pack_h2(h2, h3));
            *(uint2*)&Bls[k][cq * 4] = make_uint2(pack_h2(l0, l1), pack_h2(l2, l3));
        }
        __syncthreads();

        int kn = kc + 32;
        if (kn < 128) {
#pragma unroll
            for (int i = 0; i < 4; i++) {
                int f = tid + i * 256;
                int r = f >> 3, kq = f & 7;
                int grow = rowBase + r;
                pa[i] = (grow < M) ? *(const float4*)&A[(size_t)grow * 128 + kn + kq * 4]
                                   : make_float4(0.f, 0.f, 0.f, 0.f);
            }
#pragma unroll
            for (int i = 0; i < 2; i++) {
                int f = tid + i * 256;
                int k = f >> 4, cq = f & 15;
                int c0 = colBase + cq * 4;
                pb[i] = (c0 < Ncols) ? *(const float4*)&W[(size_t)(kn + k) * Ncols + c0]
                                     : make_float4(0.f, 0.f, 0.f, 0.f);
            }
        }

#pragma unroll
        for (int ks = 0; ks < 2; ks++) {
            const int ko = ks * 16;

            uint32_t bh[4][2], bl[4][2];
#pragma unroll
            for (int nt = 0; nt < 4; nt++) {
                int n0 = wn + nt * 8;
                uint32_t boff = (uint32_t)(((ko + bRow) * 72 + n0) * 2);
                ldsm_x2t(bh[nt][0], bh[nt][1], sBh + boff);
                ldsm_x2t(bl[nt][0], bl[nt][1], sBl + boff);
            }

#pragma unroll
            for (int mt = 0; mt < 2; mt++) {
                int r0 = wm + mt * 16;
                uint32_t aoff = (uint32_t)(((r0 + aRow) * 40 + ko + aCol) * 2);
                uint32_t a0, a1, a2, a3, l0, l1, l2, l3;
                ldsm_x4(a0, a1, a2, a3, sAh + aoff);
                ldsm_x4(l0, l1, l2, l3, sAl + aoff);
#pragma unroll
                for (int nt = 0; nt < 4; nt++)
                    mma_f16(acc[mt][nt], a0, a1, a2, a3, bh[nt][0], bh[nt][1]);
#pragma unroll
                for (int nt = 0; nt < 4; nt++)
                    mma_f16(acc[mt][nt], l0, l1, l2, l3, bh[nt][0], bh[nt][1]);
#pragma unroll
                for (int nt = 0; nt < 4; nt++)
                    mma_f16(acc[mt][nt], a0, a1, a2, a3, bl[nt][0], bl[nt][1]);
            }
        }
        __syncthreads();
    }

#pragma unroll
    for (int mt = 0; mt < 2; mt++) {
#pragma unroll
        for (int nt = 0; nt < 4; nt++) {
            int col = colBase + wn + nt * 8 + 2 * tg;
            if (col >= Ncols) continue;
            int r0 = rowBase + wm + mt * 16 + g;
            int r1 = r0 + 8;
            if (r0 < M)
                *(__half2*)&C[(size_t)r0 * Ncols + col] =
                    __floats2half2_rn(acc[mt][nt][0], acc[mt][nt][1]);
            if (r1 < M)
                *(__half2*)&C[(size_t)r1 * Ncols + col] =
                    __floats2half2_rn(acc[mt][nt][2], acc[mt][nt][3]);
        }
    }
}

// ---------------- fused CSR gather for F=128 (fp16 in, 2 nodes/warp) ---------
// Each 16-lane half-warp owns one node: lane covers 8 features (uint4 = 16B).
// Two independent edge streams per warp -> 2x memory-level parallelism.
// out[d] = relu( dis[d] * ( h[d]*dis[d] + sum_{s in N(d)} h[s]*dis[s] ) + b )
__global__ __launch_bounds__(256) void gather128_kernel(
    const __half* __restrict__ h, float* __restrict__ out,
    const float* __restrict__ bias, int do_relu)
{
    int warp = threadIdx.x >> 5;
    int lane = threadIdx.x & 31;
    int half = lane >> 4;                 // 0 or 1: which node in this warp
    int hl   = lane & 15;                 // lane within half-warp
    int node = blockIdx.x * 16 + warp * 2 + half;
    if (node >= N_NODES) return;

    const int fo = hl * 8;                // feature offset (8 fp16 per lane)
    float dd = g_dis[node];

    float acc[8], acc2[8];
    {
        uint4 u = *(const uint4*)(h + (size_t)node * 128 + fo);
        float2 f0 = __half22float2(*(__half2*)&u.x);
        float2 f1 = __half22float2(*(__half2*)&u.y);
        float2 f2 = __half22float2(*(__half2*)&u.z);
        float2 f3 = __half22float2(*(__half2*)&u.w);
        acc[0] = f0.x * dd; acc[1] = f0.y * dd;
        acc[2] = f1.x * dd; acc[3] = f1.y * dd;
        acc[4] = f2.x * dd; acc[5] = f2.y * dd;
        acc[6] = f3.x * dd; acc[7] = f3.y * dd;
#pragma unroll
        for (int i = 0; i < 8; i++) acc2[i] = 0.f;
    }

    int e   = g_rowptr[node];
    int end = g_rowptr[node + 1];

    for (; e + 3 < end; e += 4) {
        int s0 = g_csrc[e];
        int s1 = g_csrc[e + 1];
        int s2 = g_csrc[e + 2];
        int s3 = g_csrc[e + 3];
        float d0 = g_dis[s0], d1 = g_dis[s1], d2 = g_dis[s2], d3 = g_dis[s3];
        uint4 u0 = *(const uint4*)(h + (size_t)s0 * 128 + fo);
        uint4 u1 = *(const uint4*)(h + (size_t)s1 * 128 + fo);
        uint4 u2 = *(const uint4*)(h + (size_t)s2 * 128 + fo);
        uint4 u3 = *(const uint4*)(h + (size_t)s3 * 128 + fo);
#pragma unroll
        for (int p = 0; p < 4; p++) {
            uint32_t w0 = (&u0.x)[p], w1 = (&u1.x)[p], w2 = (&u2.x)[p], w3 = (&u3.x)[p];
            float2 f0 = __half22float2(*(__half2*)&w0);
            float2 f1 = __half22float2(*(__half2*)&w1);
            float2 f2 = __half22float2(*(__half2*)&w2);
            float2 f3 = __half22float2(*(__half2*)&w3);
            acc [2*p]   += f0.x * d0 + f2.x * d2;
            acc [2*p+1] += f0.y * d0 + f2.y * d2;
            acc2[2*p]   += f1.x * d1 + f3.x * d3;
            acc2[2*p+1] += f1.y * d1 + f3.y * d3;
        }
    }
    for (; e < end; e++) {
        int s0 = g_csrc[e];
        float d0 = g_dis[s0];
        uint4 u0 = *(const uint4*)(h + (size_t)s0 * 128 + fo);
#pragma unroll
        for (int p = 0; p < 4; p++) {
            uint32_t w0 = (&u0.x)[p];
            float2 f0 = __half22float2(*(__half2*)&w0);
            acc[2*p]   += f0.x * d0;
            acc[2*p+1] += f0.y * d0;
        }
    }

    float4 b0 = *(const float4*)&bias[fo];
    float4 b1 = *(const float4*)&bias[fo + 4];
    float r[8];
#pragma unroll
    for (int i = 0; i < 8; i++) {
        float bv = (i < 4) ? (&b0.x)[i] : (&b1.x)[i - 4];
        r[i] = (acc[i] + acc2[i]) * dd + bv;
        if (do_relu) r[i] = fmaxf(r[i], 0.f);
    }
    float* orow = out + (size_t)node * 128 + fo;
    *(float4*)orow       = make_float4(r[0], r[1], r[2], r[3]);
    *(float4*)(orow + 4) = make_float4(r[4], r[5], r[6], r[7]);
}

// ------- fused CSR gather (F=40, fp16 in) + bias + log-softmax ---------------
// lanes 0..19 each own classes {2*lane, 2*lane+1}
__global__ __launch_bounds__(256) void gather40_softmax_kernel(
    const __half* __restrict__ h, const float* __restrict__ bias,
    float* __restrict__ out)
{
    int warp = threadIdx.x >> 5;
    int lane = threadIdx.x & 31;
    int node = blockIdx.x * 8 + warp;
    if (node >= N_NODES) return;

    const bool act = (lane < 20);
    float dd = g_dis[node];
    float accA = 0.f, accB = 0.f;
    if (act) {
        __half2 v = *(const __half2*)(h + (size_t)node * N_CLS + lane * 2);
        float2 f = __half22float2(v);
        accA = f.x * dd; accB = f.y * dd;
    }

    int e   = g_rowptr[node];
    int end = g_rowptr[node + 1];
    for (; e + 1 < end; e += 2) {
        int s0 = g_csrc[e];
        int s1 = g_csrc[e + 1];
        float d0 = g_dis[s0];
        float d1 = g_dis[s1];
        if (act) {
            float2 f0 = __half22float2(*(const __half2*)(h + (size_t)s0 * N_CLS + lane * 2));
            float2 f1 = __half22float2(*(const __half2*)(h + (size_t)s1 * N_CLS + lane * 2));
            accA += f0.x * d0 + f1.x * d1;
            accB += f0.y * d0 + f1.y * d1;
        }
    }
    if (e < end) {
        int s0 = g_csrc[e];
        float d0 = g_dis[s0];
        if (act) {
            float2 f0 = __half22float2(*(const __half2*)(h + (size_t)s0 * N_CLS + lane * 2));
            accA += f0.x * d0;
            accB += f0.y * d0;
        }
    }

    float a = act ? (accA * dd + bias[lane * 2])     : -INFINITY;
    float b = act ? (accB * dd + bias[lane * 2 + 1]) : -INFINITY;

    float m = fmaxf(a, b);
#pragma unroll
    for (int off = 16; off > 0; off >>= 1)
        m = fmaxf(m, __shfl_xor_sync(0xFFFFFFFFu, m, off));

    float s = act ? (expf(a - m) + expf(b - m)) : 0.f;
#pragma unroll
    for (int off = 16; off > 0; off >>= 1)
        s += __shfl_xor_sync(0xFFFFFFFFu, s, off);

    float lse = m + logf(s);
    if (act) {
        float2 r = make_float2(a - lse, b - lse);
        *(float2*)&out[(size_t)node * N_CLS + lane * 2] = r;
    }
}

// ---------------- launch ------------------------------------------------------
extern "C" void kernel_launch(void* const* d_in, const int* in_sizes, int n_in,
                              void* d_out, int out_size) {
    const float* x  = (const float*)d_in[0];
    const int*   ei = (const int*)d_in[1];      // int32 [2][N_EDGES]
    const float* W1 = (const float*)d_in[2];
    const float* b1 = (const float*)d_in[3];
    const float* W2 = (const float*)d_in[4];
    const float* b2 = (const float*)d_in[5];
    const float* W3 = (const float*)d_in[6];
    const float* b3 = (const float*)d_in[7];
    float* out = (float*)d_out;

    __half* t_ptr;
    float*  x_ptr;
    cudaGetSymbolAddress((void**)&t_ptr, g_t);
    cudaGetSymbolAddress((void**)&x_ptr, g_x);

    static cudaStream_t s2 = nullptr;
    static cudaEvent_t evFork = nullptr, evJoin = nullptr;
    if (s2 == nullptr) {
        cudaStreamCreateWithFlags(&s2, cudaStreamNonBlocking);
        cudaEventCreateWithFlags(&evFork, cudaEventDisableTiming);
        cudaEventCreateWithFlags(&evJoin, cudaEventDisableTiming);
    }

    const int gemmGridX  = (N_NODES + 127) / 128;
    const dim3 gemmGrid128(gemmGridX, 2);   // 128 cols -> 2 n-blocks
    const dim3 gemmGrid40(gemmGridX, 1);    // 40 cols  -> 1 n-block
    const int gather128Grid = (N_NODES + 15) / 16;
    const int gather40Grid  = (N_NODES + 7) / 8;

    // ---- fork: CSR build on s2, gemm1 at capture idx 3 ----
    cudaEventRecord(evFork, 0);
    cudaStreamWaitEvent(s2, evFork, 0);

    zero_deg_kernel<<<(N_NODES + 255) / 256, 256, 0, s2>>>();   // idx 0
    hist_deg_kernel<<<(N_EDGES + 255) / 256, 256, 0, s2>>>(ei); // idx 1
    scan_kernel<<<1, 1024, 0, s2>>>();                           // idx 2

    gemm_f16x3_kernel<<<gemmGrid128, 256>>>(x, W1, t_ptr, N_NODES, 128); // idx 3 (profiled)

    csr_fill_kernel<<<(N_EDGES + 255) / 256, 256, 0, s2>>>(ei); // idx 4
    cudaEventRecord(evJoin, s2);

    // ---- join: gather-1 needs both CSR and GEMM-1 ----
    cudaStreamWaitEvent(0, evJoin, 0);
    gather128_kernel<<<gather128Grid, 256>>>(t_ptr, x_ptr, b1, 1);

    // ---- layer 2 ----
    gemm_f16x3_kernel<<<gemmGrid128, 256>>>(x_ptr, W2, t_ptr, N_NODES, 128);
    gather128_kernel<<<gather128Grid, 256>>>(t_ptr, x_ptr, b2, 1);

    // ---- layer 3 (40 cols) + fused log-softmax ----
    gemm_f16x3_kernel<<<gemmGrid40, 256>>>(x_ptr, W3, t_ptr, N_NODES, N_CLS);
    gather40_softmax_kernel<<<gather40Grid, 256>>>(t_ptr, b3, out);
}

// round 14
// speedup vs baseline: 1.8281x; 1.8281x over previous
#include <cuda_runtime.h>
#include <cuda_fp16.h>
#include <stdint.h>
#include <math.h>

#define N_NODES 100000
#define N_EDGES 1600000
#define N_CLS   40
#define SCAN_BLOCKS 98   // ceil(100000 / 1024)

// ---------------- scratch (static device arrays; no cudaMalloc) -------------
__device__ __half g_t[(size_t)N_NODES * 128];   // transform output (x @ W), fp16
__device__ float  g_x[(size_t)N_NODES * 128];   // layer activation buffer, fp32
__device__ int    g_deg[N_NODES];
__device__ float  g_dis[N_NODES];               // (deg+1)^{-1/2}
__device__ int    g_rowptr[N_NODES + 1];
__device__ int    g_cursor[N_NODES];
__device__ int    g_csrc[N_EDGES];              // CSR: src ids grouped by dst
__device__ int    g_bsum[128];                  // per-block degree sums
__device__ int    g_boff[128];                  // exclusive block offsets

// ---------------- degree histogram ------------------------------------------
__global__ void zero_deg_kernel() {
    int i = blockIdx.x * blockDim.x + threadIdx.x;
    if (i < N_NODES) g_deg[i] = 0;
}

__global__ void hist_deg_kernel(const int* __restrict__ ei) {
    int e = blockIdx.x * blockDim.x + threadIdx.x;
    if (e < N_EDGES) atomicAdd(&g_deg[ei[N_EDGES + e]], 1);
}

// ---------------- 3-phase coalesced scan -------------------------------------
// Phase 1: per-block sums of deg (coalesced).
__global__ __launch_bounds__(1024) void scan_p1_kernel() {
    int i = blockIdx.x * 1024 + threadIdx.x;
    int v = (i < N_NODES) ? g_deg[i] : 0;
    int lane = threadIdx.x & 31, wid = threadIdx.x >> 5;
#pragma unroll
    for (int off = 16; off > 0; off >>= 1)
        v += __shfl_down_sync(0xFFFFFFFFu, v, off);
    __shared__ int ws[32];
    if (lane == 0) ws[wid] = v;
    __syncthreads();
    if (wid == 0) {
        int s = ws[lane];
#pragma unroll
        for (int off = 16; off > 0; off >>= 1)
            s += __shfl_down_sync(0xFFFFFFFFu, s, off);
        if (lane == 0) g_bsum[blockIdx.x] = s;
    }
}

// Phase 2: exclusive scan of SCAN_BLOCKS block sums (one tiny block).
__global__ void scan_p2_kernel() {
    __shared__ int s[SCAN_BLOCKS];
    int t = threadIdx.x;
    if (t < SCAN_BLOCKS) s[t] = g_bsum[t];
    __syncthreads();
    if (t == 0) {
        int run = 0;
        for (int i = 0; i < SCAN_BLOCKS; i++) {
            int v = s[i];
            s[i] = run;
            run += v;
        }
    }
    __syncthreads();
    if (t < SCAN_BLOCKS) g_boff[t] = s[t];
}

// Phase 3: block-local exclusive scan + write rowptr/cursor/dis (coalesced).
__global__ __launch_bounds__(1024) void scan_p3_kernel() {
    int i = blockIdx.x * 1024 + threadIdx.x;
    int lane = threadIdx.x & 31, wid = threadIdx.x >> 5;
    int val = (i < N_NODES) ? g_deg[i] : 0;

    int x = val;
#pragma unroll
    for (int off = 1; off < 32; off <<= 1) {
        int n = __shfl_up_sync(0xFFFFFFFFu, x, off);
        if (lane >= off) x += n;
    }
    __shared__ int ws[32];
    if (lane == 31) ws[wid] = x;
    __syncthreads();
    if (wid == 0) {
        int y = ws[lane];
#pragma unroll
        for (int off = 1; off < 32; off <<= 1) {
            int n = __shfl_up_sync(0xFFFFFFFFu, y, off);
            if (lane >= off) y += n;
        }
        ws[lane] = y;
    }
    __syncthreads();
    int woff = (wid > 0) ? ws[wid - 1] : 0;
    int incl = x + woff;
    int excl = incl - val;
    int base = g_boff[blockIdx.x];

    if (i < N_NODES) {
        int p = base + excl;
        g_rowptr[i] = p;
        g_cursor[i] = p;
        g_dis[i] = rsqrtf((float)(val + 1));
        if (i == N_NODES - 1) g_rowptr[N_NODES] = base + incl;
    }
}

__global__ void csr_fill_kernel(const int* __restrict__ ei) {
    int e = blockIdx.x * blockDim.x + threadIdx.x;
    if (e < N_EDGES) {
        int s = ei[e];
        int d = ei[N_EDGES + e];
        int pos = atomicAdd(&g_cursor[d], 1);
        g_csrc[pos] = s;
    }
}

// ---------------- helpers ----------------------------------------------------
__device__ __forceinline__ void h_split(float x, __half& hi, __half& lo) {
    __half h = __float2half_rn(x);
    hi = h;
    lo = __float2half_rn(x - __half2float(h));
}

__device__ __forceinline__ uint32_t pack_h2(__half a, __half b) {
    __half2 h = __halves2half2(a, b);
    return *(uint32_t*)&h;
}

__device__ __forceinline__ void mma_f16(float* c, uint32_t a0, uint32_t a1,
                                        uint32_t a2, uint32_t a3,
                                        uint32_t b0, uint32_t b1) {
    asm volatile(
        "mma.sync.aligned.m16n8k16.row.col.f32.f16.f16.f32 "
        "{%0,%1,%2,%3}, {%4,%5,%6,%7}, {%8,%9}, {%0,%1,%2,%3};"
        : "+f"(c[0]), "+f"(c[1]), "+f"(c[2]), "+f"(c[3])
        : "r"(a0), "r"(a1), "r"(a2), "r"(a3), "r"(b0), "r"(b1));
}

__device__ __forceinline__ void ldsm_x4(uint32_t& r0, uint32_t& r1,
                                        uint32_t& r2, uint32_t& r3, uint32_t addr) {
    asm volatile("ldmatrix.sync.aligned.m8n8.x4.shared.b16 {%0,%1,%2,%3}, [%4];"
                 : "=r"(r0), "=r"(r1), "=r"(r2), "=r"(r3) : "r"(addr));
}

__device__ __forceinline__ void ldsm_x2t(uint32_t& r0, uint32_t& r1, uint32_t addr) {
    asm volatile("ldmatrix.sync.aligned.m8n8.x2.trans.shared.b16 {%0,%1}, [%2];"
                 : "=r"(r0), "=r"(r1) : "r"(addr));
}

// ---------------- 3-term fp16 tensor-core GEMM (ldmatrix) --------------------
__global__ __launch_bounds__(256, 2) void gemm_f16x3_kernel(
    const float* __restrict__ A, const float* __restrict__ W,
    __half* __restrict__ C, int M, int Ncols)
{
    __shared__ __half Ahs[128][40];
    __shared__ __half Als[128][40];
    __shared__ __half Bhs[32][72];
    __shared__ __half Bls[32][72];

    const int tid  = threadIdx.x;
    const int warp = tid >> 5;
    const int lane = tid & 31;
    const int g    = lane >> 2;
    const int tg   = lane & 3;
    const int wm   = (warp >> 1) * 32;
    const int wn   = (warp & 1) * 32;
    const int rowBase = blockIdx.x * 128;
    const int colBase = blockIdx.y * 64;

    const int li   = lane & 7;
    const int quad = lane >> 3;
    const int aRow = li + (quad & 1) * 8;
    const int aCol = (quad >> 1) * 8;
    const int bRow = ((lane >> 3) & 1) * 8 + li;

    const uint32_t sAh = (uint32_t)__cvta_generic_to_shared(&Ahs[0][0]);
    const uint32_t sAl = (uint32_t)__cvta_generic_to_shared(&Als[0][0]);
    const uint32_t sBh = (uint32_t)__cvta_generic_to_shared(&Bhs[0][0]);
    const uint32_t sBl = (uint32_t)__cvta_generic_to_shared(&Bls[0][0]);

    float acc[2][4][4];
#pragma unroll
    for (int mt = 0; mt < 2; mt++)
#pragma unroll
        for (int nt = 0; nt < 4; nt++)
#pragma unroll
            for (int i = 0; i < 4; i++) acc[mt][nt][i] = 0.f;

    float4 pa[4], pb[2];
#pragma unroll
    for (int i = 0; i < 4; i++) {
        int f = tid + i * 256;
        int r = f >> 3, kq = f & 7;
        int grow = rowBase + r;
        pa[i] = (grow < M) ? *(const float4*)&A[(size_t)grow * 128 + kq * 4]
                           : make_float4(0.f, 0.f, 0.f, 0.f);
    }
#pragma unroll
    for (int i = 0; i < 2; i++) {
        int f = tid + i * 256;
        int k = f >> 4, cq = f & 15;
        int c0 = colBase + cq * 4;
        pb[i] = (c0 < Ncols) ? *(const float4*)&W[(size_t)k * Ncols + c0]
                             : make_float4(0.f, 0.f, 0.f, 0.f);
    }

    for (int kc = 0; kc < 128; kc += 32) {
#pragma unroll
        for (int i = 0; i < 4; i++) {
            int f = tid + i * 256;
            int r = f >> 3, kq = f & 7;
            __half h0, l0, h1, l1, h2, l2, h3, l3;
            h_split(pa[i].x, h0, l0); h_split(pa[i].y, h1, l1);
            h_split(pa[i].z, h2, l2); h_split(pa[i].w, h3, l3);
            *(uint2*)&Ahs[r][kq * 4] = make_uint2(pack_h2(h0, h1), pack_h2(h2, h3));
            *(uint2*)&Als[r][kq * 4] = make_uint2(pack_h2(l0, l1), pack_h2(l2, l3));
        }
#pragma unroll
        for (int i = 0; i < 2; i++) {
            int f = tid + i * 256;
            int k = f >> 4, cq = f & 15;
            __half h0, l0, h1, l1, h2, l2, h3, l3;
            h_split(pb[i].x, h0, l0); h_split(pb[i].y, h1, l1);
            h_split(pb[i].z, h2, l2); h_split(pb[i].w, h3, l3);
            *(uint2*)&Bhs[k][cq * 4] = make_uint2(pack_h2(h0, h1), pack_h2(h2, h3));
            *(uint2*)&Bls[k][cq * 4] = make_uint2(pack_h2(l0, l1), pack_h2(l2, l3));
        }
        __syncthreads();

        int kn = kc + 32;
        if (kn < 128) {
#pragma unroll
            for (int i = 0; i < 4; i++) {
                int f = tid + i * 256;
                int r = f >> 3, kq = f & 7;
                int grow = rowBase + r;
                pa[i] = (grow < M) ? *(const float4*)&A[(size_t)grow * 128 + kn + kq * 4]
                                   : make_float4(0.f, 0.f, 0.f, 0.f);
            }
#pragma unroll
            for (int i = 0; i < 2; i++) {
                int f = tid + i * 256;
                int k = f >> 4, cq = f & 15;
                int c0 = colBase + cq * 4;
                pb[i] = (c0 < Ncols) ? *(const float4*)&W[(size_t)(kn + k) * Ncols + c0]
                                     : make_float4(0.f, 0.f, 0.f, 0.f);
            }
        }

#pragma unroll
        for (int ks = 0; ks < 2; ks++) {
            const int ko = ks * 16;

            uint32_t bh[4][2], bl[4][2];
#pragma unroll
            for (int nt = 0; nt < 4; nt++) {
                int n0 = wn + nt * 8;
                uint32_t boff = (uint32_t)(((ko + bRow) * 72 + n0) * 2);
                ldsm_x2t(bh[nt][0], bh[nt][1], sBh + boff);
                ldsm_x2t(bl[nt][0], bl[nt][1], sBl + boff);
            }

#pragma unroll
            for (int mt = 0; mt < 2; mt++) {
                int r0 = wm + mt * 16;
                uint32_t aoff = (uint32_t)(((r0 + aRow) * 40 + ko + aCol) * 2);
                uint32_t a0, a1, a2, a3, l0, l1, l2, l3;
                ldsm_x4(a0, a1, a2, a3, sAh + aoff);
                ldsm_x4(l0, l1, l2, l3, sAl + aoff);
#pragma unroll
                for (int nt = 0; nt < 4; nt++)
                    mma_f16(acc[mt][nt], a0, a1, a2, a3, bh[nt][0], bh[nt][1]);
#pragma unroll
                for (int nt = 0; nt < 4; nt++)
                    mma_f16(acc[mt][nt], l0, l1, l2, l3, bh[nt][0], bh[nt][1]);
#pragma unroll
                for (int nt = 0; nt < 4; nt++)
                    mma_f16(acc[mt][nt], a0, a1, a2, a3, bl[nt][0], bl[nt][1]);
            }
        }
        __syncthreads();
    }

#pragma unroll
    for (int mt = 0; mt < 2; mt++) {
#pragma unroll
        for (int nt = 0; nt < 4; nt++) {
            int col = colBase + wn + nt * 8 + 2 * tg;
            if (col >= Ncols) continue;
            int r0 = rowBase + wm + mt * 16 + g;
            int r1 = r0 + 8;
            if (r0 < M)
                *(__half2*)&C[(size_t)r0 * Ncols + col] =
                    __floats2half2_rn(acc[mt][nt][0], acc[mt][nt][1]);
            if (r1 < M)
                *(__half2*)&C[(size_t)r1 * Ncols + col] =
                    __floats2half2_rn(acc[mt][nt][2], acc[mt][nt][3]);
        }
    }
}

// ---------------- fused CSR gather for F=128 (fp16 input, R12 version) -------
__global__ __launch_bounds__(256) void gather128_kernel(
    const __half* __restrict__ h, float* __restrict__ out,
    const float* __restrict__ bias, int do_relu)
{
    int warp = threadIdx.x >> 5;
    int lane = threadIdx.x & 31;
    int node = blockIdx.x * 8 + warp;
    if (node >= N_NODES) return;

    float dd = g_dis[node];
    float4 acc0, acc1;
    {
        uint2 u = *(const uint2*)(h + (size_t)node * 128 + lane * 4);
        float2 f01 = __half22float2(*(__half2*)&u.x);
        float2 f23 = __half22float2(*(__half2*)&u.y);
        acc0 = make_float4(f01.x * dd, f01.y * dd, f23.x * dd, f23.y * dd);
        acc1 = make_float4(0.f, 0.f, 0.f, 0.f);
    }

    int e   = g_rowptr[node];
    int end = g_rowptr[node + 1];

    for (; e + 3 < end; e += 4) {
        int s0 = g_csrc[e];
        int s1 = g_csrc[e + 1];
        int s2 = g_csrc[e + 2];
        int s3 = g_csrc[e + 3];
        float d0 = g_dis[s0], d1 = g_dis[s1], d2 = g_dis[s2], d3 = g_dis[s3];
        uint2 u0 = *(const uint2*)(h + (size_t)s0 * 128 + lane * 4);
        uint2 u1 = *(const uint2*)(h + (size_t)s1 * 128 + lane * 4);
        uint2 u2 = *(const uint2*)(h + (size_t)s2 * 128 + lane * 4);
        uint2 u3 = *(const uint2*)(h + (size_t)s3 * 128 + lane * 4);
        float2 a01 = __half22float2(*(__half2*)&u0.x), a23 = __half22float2(*(__half2*)&u0.y);
        float2 b01 = __half22float2(*(__half2*)&u1.x), b23 = __half22float2(*(__half2*)&u1.y);
        float2 c01 = __half22float2(*(__half2*)&u2.x), c23 = __half22float2(*(__half2*)&u2.y);
        float2 e01 = __half22float2(*(__half2*)&u3.x), e23 = __half22float2(*(__half2*)&u3.y);
        acc0.x += a01.x * d0 + c01.x * d2;
        acc0.y += a01.y * d0 + c01.y * d2;
        acc0.z += a23.x * d0 + c23.x * d2;
        acc0.w += a23.y * d0 + c23.y * d2;
        acc1.x += b01.x * d1 + e01.x * d3;
        acc1.y += b01.y * d1 + e01.y * d3;
        acc1.z += b23.x * d1 + e23.x * d3;
        acc1.w += b23.y * d1 + e23.y * d3;
    }
    for (; e < end; e++) {
        int s0 = g_csrc[e];
        float d0 = g_dis[s0];
        uint2 u0 = *(const uint2*)(h + (size_t)s0 * 128 + lane * 4);
        float2 a01 = __half22float2(*(__half2*)&u0.x), a23 = __half22float2(*(__half2*)&u0.y);
        acc0.x += a01.x * d0; acc0.y += a01.y * d0; acc0.z += a23.x * d0; acc0.w += a23.y * d0;
    }

    float4 b = *(const float4*)&bias[lane * 4];
    float4 r;
    r.x = (acc0.x + acc1.x) * dd + b.x;
    r.y = (acc0.y + acc1.y) * dd + b.y;
    r.z = (acc0.z + acc1.z) * dd + b.z;
    r.w = (acc0.w + acc1.w) * dd + b.w;
    if (do_relu) {
        r.x = fmaxf(r.x, 0.f); r.y = fmaxf(r.y, 0.f);
        r.z = fmaxf(r.z, 0.f); r.w = fmaxf(r.w, 0.f);
    }
    *(float4*)&out[(size_t)node * 128 + lane * 4] = r;
}

// ------- fused CSR gather (F=40, fp16 in) + bias + log-softmax ---------------
__global__ __launch_bounds__(256) void gather40_softmax_kernel(
    const __half* __restrict__ h, const float* __restrict__ bias,
    float* __restrict__ out)
{
    int warp = threadIdx.x >> 5;
    int lane = threadIdx.x & 31;
    int node = blockIdx.x * 8 + warp;
    if (node >= N_NODES) return;

    const bool act = (lane < 20);
    float dd = g_dis[node];
    float accA = 0.f, accB = 0.f;
    if (act) {
        __half2 v = *(const __half2*)(h + (size_t)node * N_CLS + lane * 2);
        float2 f = __half22float2(v);
        accA = f.x * dd; accB = f.y * dd;
    }

    int e   = g_rowptr[node];
    int end = g_rowptr[node + 1];
    for (; e + 1 < end; e += 2) {
        int s0 = g_csrc[e];
        int s1 = g_csrc[e + 1];
        float d0 = g_dis[s0];
        float d1 = g_dis[s1];
        if (act) {
            float2 f0 = __half22float2(*(const __half2*)(h + (size_t)s0 * N_CLS + lane * 2));
            float2 f1 = __half22float2(*(const __half2*)(h + (size_t)s1 * N_CLS + lane * 2));
            accA += f0.x * d0 + f1.x * d1;
            accB += f0.y * d0 + f1.y * d1;
        }
    }
    if (e < end) {
        int s0 = g_csrc[e];
        float d0 = g_dis[s0];
        if (act) {
            float2 f0 = __half22float2(*(const __half2*)(h + (size_t)s0 * N_CLS + lane * 2));
            accA += f0.x * d0;
            accB += f0.y * d0;
        }
    }

    float a = act ? (accA * dd + bias[lane * 2])     : -INFINITY;
    float b = act ? (accB * dd + bias[lane * 2 + 1]) : -INFINITY;

    float m = fmaxf(a, b);
#pragma unroll
    for (int off = 16; off > 0; off >>= 1)
        m = fmaxf(m, __shfl_xor_sync(0xFFFFFFFFu, m, off));

    float s = act ? (expf(a - m) + expf(b - m)) : 0.f;
#pragma unroll
    for (int off = 16; off > 0; off >>= 1)
        s += __shfl_xor_sync(0xFFFFFFFFu, s, off);

    float lse = m + logf(s);
    if (act) {
        float2 r = make_float2(a - lse, b - lse);
        *(float2*)&out[(size_t)node * N_CLS + lane * 2] = r;
    }
}

// ---------------- launch ------------------------------------------------------
extern "C" void kernel_launch(void* const* d_in, const int* in_sizes, int n_in,
                              void* d_out, int out_size) {
    const float* x  = (const float*)d_in[0];
    const int*   ei = (const int*)d_in[1];      // int32 [2][N_EDGES]
    const float* W1 = (const float*)d_in[2];
    const float* b1 = (const float*)d_in[3];
    const float* W2 = (const float*)d_in[4];
    const float* b2 = (const float*)d_in[5];
    const float* W3 = (const float*)d_in[6];
    const float* b3 = (const float*)d_in[7];
    float* out = (float*)d_out;

    __half* t_ptr;
    float*  x_ptr;
    cudaGetSymbolAddress((void**)&t_ptr, g_t);
    cudaGetSymbolAddress((void**)&x_ptr, g_x);

    static cudaStream_t s2 = nullptr;
    static cudaEvent_t evFork = nullptr, evJoin = nullptr;
    if (s2 == nullptr) {
        cudaStreamCreateWithFlags(&s2, cudaStreamNonBlocking);
        cudaEventCreateWithFlags(&evFork, cudaEventDisableTiming);
        cudaEventCreateWithFlags(&evJoin, cudaEventDisableTiming);
    }

    const int gemmGridX  = (N_NODES + 127) / 128;
    const dim3 gemmGrid128(gemmGridX, 2);   // 128 cols -> 2 n-blocks
    const dim3 gemmGrid40(gemmGridX, 1);    // 40 cols  -> 1 n-block
    const int gatherGrid = (N_NODES + 7) / 8;

    // ---- fork: CSR build on s2 (fast coalesced scan), gemm-1 on main -------
    cudaEventRecord(evFork, 0);
    cudaStreamWaitEvent(s2, evFork, 0);

    zero_deg_kernel<<<(N_NODES + 255) / 256, 256, 0, s2>>>();
    hist_deg_kernel<<<(N_EDGES + 255) / 256, 256, 0, s2>>>(ei);
    scan_p1_kernel<<<SCAN_BLOCKS, 1024, 0, s2>>>();
    scan_p2_kernel<<<1, 128, 0, s2>>>();
    scan_p3_kernel<<<SCAN_BLOCKS, 1024, 0, s2>>>();
    csr_fill_kernel<<<(N_EDGES + 255) / 256, 256, 0, s2>>>(ei);
    cudaEventRecord(evJoin, s2);

    gemm_f16x3_kernel<<<gemmGrid128, 256>>>(x, W1, t_ptr, N_NODES, 128);

    // ---- join: gather-1 needs both CSR and GEMM-1 ----
    cudaStreamWaitEvent(0, evJoin, 0);
    gather128_kernel<<<gatherGrid, 256>>>(t_ptr, x_ptr, b1, 1);

    // ---- layer 2 ----
    gemm_f16x3_kernel<<<gemmGrid128, 256>>>(x_ptr, W2, t_ptr, N_NODES, 128);
    gather128_kernel<<<gatherGrid, 256>>>(t_ptr, x_ptr, b2, 1);

    // ---- layer 3 (40 cols) + fused log-softmax ----
    gemm_f16x3_kernel<<<gemmGrid40, 256>>>(x_ptr, W3, t_ptr, N_NODES, N_CLS);
    gather40_softmax_kernel<<<gatherGrid, 256>>>(t_ptr, b3, out);
}

// round 15
// speedup vs baseline: 1.9464x; 1.0647x over previous
#include <cuda_runtime.h>
#include <cuda_fp16.h>
#include <stdint.h>
#include <math.h>

#define N_NODES 100000
#define N_EDGES 1600000
#define N_CLS   40
#define SCAN_BLOCKS 98   // ceil(100000 / 1024)

// ---------------- scratch (static device arrays; no cudaMalloc) -------------
__device__ __half g_t[(size_t)N_NODES * 128];   // transform output (x @ W), fp16
__device__ float  g_x[(size_t)N_NODES * 128];   // layer activation buffer, fp32
__device__ int    g_deg[N_NODES];
__device__ float  g_dis[N_NODES];               // (deg+1)^{-1/2}
__device__ int    g_rowptr[N_NODES + 1];
__device__ int    g_cursor[N_NODES];
__device__ int    g_csrc[N_EDGES];              // CSR: src ids grouped by dst
__device__ int    g_bsum[128];                  // per-block degree sums
__device__ int    g_boff[128];                  // exclusive block offsets

// ---------------- degree histogram ------------------------------------------
__global__ void zero_deg_kernel() {
    int i = blockIdx.x * blockDim.x + threadIdx.x;
    if (i < N_NODES) g_deg[i] = 0;
}

__global__ void hist_deg_kernel(const int* __restrict__ ei) {
    int e = blockIdx.x * blockDim.x + threadIdx.x;
    if (e < N_EDGES) atomicAdd(&g_deg[ei[N_EDGES + e]], 1);
}

// ---------------- 3-phase coalesced scan -------------------------------------
__global__ __launch_bounds__(1024) void scan_p1_kernel() {
    int i = blockIdx.x * 1024 + threadIdx.x;
    int v = (i < N_NODES) ? g_deg[i] : 0;
    int lane = threadIdx.x & 31, wid = threadIdx.x >> 5;
#pragma unroll
    for (int off = 16; off > 0; off >>= 1)
        v += __shfl_down_sync(0xFFFFFFFFu, v, off);
    __shared__ int ws[32];
    if (lane == 0) ws[wid] = v;
    __syncthreads();
    if (wid == 0) {
        int s = ws[lane];
#pragma unroll
        for (int off = 16; off > 0; off >>= 1)
            s += __shfl_down_sync(0xFFFFFFFFu, s, off);
        if (lane == 0) g_bsum[blockIdx.x] = s;
    }
}

__global__ void scan_p2_kernel() {
    __shared__ int s[SCAN_BLOCKS];
    int t = threadIdx.x;
    if (t < SCAN_BLOCKS) s[t] = g_bsum[t];
    __syncthreads();
    if (t == 0) {
        int run = 0;
        for (int i = 0; i < SCAN_BLOCKS; i++) {
            int v = s[i];
            s[i] = run;
            run += v;
        }
    }
    __syncthreads();
    if (t < SCAN_BLOCKS) g_boff[t] = s[t];
}

__global__ __launch_bounds__(1024) void scan_p3_kernel() {
    int i = blockIdx.x * 1024 + threadIdx.x;
    int lane = threadIdx.x & 31, wid = threadIdx.x >> 5;
    int val = (i < N_NODES) ? g_deg[i] : 0;

    int x = val;
#pragma unroll
    for (int off = 1; off < 32; off <<= 1) {
        int n = __shfl_up_sync(0xFFFFFFFFu, x, off);
        if (lane >= off) x += n;
    }
    __shared__ int ws[32];
    if (lane == 31) ws[wid] = x;
    __syncthreads();
    if (wid == 0) {
        int y = ws[lane];
#pragma unroll
        for (int off = 1; off < 32; off <<= 1) {
            int n = __shfl_up_sync(0xFFFFFFFFu, y, off);
            if (lane >= off) y += n;
        }
        ws[lane] = y;
    }
    __syncthreads();
    int woff = (wid > 0) ? ws[wid - 1] : 0;
    int incl = x + woff;
    int excl = incl - val;
    int base = g_boff[blockIdx.x];

    if (i < N_NODES) {
        int p = base + excl;
        g_rowptr[i] = p;
        g_cursor[i] = p;
        g_dis[i] = rsqrtf((float)(val + 1));
        if (i == N_NODES - 1) g_rowptr[N_NODES] = base + incl;
    }
}

__global__ void csr_fill_kernel(const int* __restrict__ ei) {
    int e = blockIdx.x * blockDim.x + threadIdx.x;
    if (e < N_EDGES) {
        int s = ei[e];
        int d = ei[N_EDGES + e];
        int pos = atomicAdd(&g_cursor[d], 1);
        g_csrc[pos] = s;
    }
}

// ---------------- helpers ----------------------------------------------------
__device__ __forceinline__ void h_split(float x, __half& hi, __half& lo) {
    __half h = __float2half_rn(x);
    hi = h;
    lo = __float2half_rn(x - __half2float(h));
}

__device__ __forceinline__ uint32_t pack_h2(__half a, __half b) {
    __half2 h = __halves2half2(a, b);
    return *(uint32_t*)&h;
}

__device__ __forceinline__ void mma_f16(float* c, uint32_t a0, uint32_t a1,
                                        uint32_t a2, uint32_t a3,
                                        uint32_t b0, uint32_t b1) {
    asm volatile(
        "mma.sync.aligned.m16n8k16.row.col.f32.f16.f16.f32 "
        "{%0,%1,%2,%3}, {%4,%5,%6,%7}, {%8,%9}, {%0,%1,%2,%3};"
        : "+f"(c[0]), "+f"(c[1]), "+f"(c[2]), "+f"(c[3])
        : "r"(a0), "r"(a1), "r"(a2), "r"(a3), "r"(b0), "r"(b1));
}

__device__ __forceinline__ void ldsm_x4(uint32_t& r0, uint32_t& r1,
                                        uint32_t& r2, uint32_t& r3, uint32_t addr) {
    asm volatile("ldmatrix.sync.aligned.m8n8.x4.shared.b16 {%0,%1,%2,%3}, [%4];"
                 : "=r"(r0), "=r"(r1), "=r"(r2), "=r"(r3) : "r"(addr));
}

__device__ __forceinline__ void ldsm_x2t(uint32_t& r0, uint32_t& r1, uint32_t addr) {
    asm volatile("ldmatrix.sync.aligned.m8n8.x2.trans.shared.b16 {%0,%1}, [%2];"
                 : "=r"(r0), "=r"(r1) : "r"(addr));
}

// ---------------- fp16 tensor-core GEMM (ldmatrix), FULL=3-term / 1-term -----
// C[M x Ncols] (fp16) = A[M x 128] (fp32) @ W[128 x Ncols] (fp32).
// FULL: hi/lo split, ah*bh + al*bh + ah*bl (~2^-22 accurate).
// !FULL: pure fp16 ah*bh (~2^-11 accurate; used for layers 2/3 where the
//        empirically-calibrated error budget allows it).
template <bool FULL>
__global__ __launch_bounds__(256, 2) void gemm_f16_kernel(
    const float* __restrict__ A, const float* __restrict__ W,
    __half* __restrict__ C, int M, int Ncols)
{
    __shared__ __half Ahs[128][40];
    __shared__ __half Als[FULL ? 128 : 1][40];
    __shared__ __half Bhs[32][72];
    __shared__ __half Bls[FULL ? 32 : 1][72];

    const int tid  = threadIdx.x;
    const int warp = tid >> 5;
    const int lane = tid & 31;
    const int g    = lane >> 2;
    const int tg   = lane & 3;
    const int wm   = (warp >> 1) * 32;
    const int wn   = (warp & 1) * 32;
    const int rowBase = blockIdx.x * 128;
    const int colBase = blockIdx.y * 64;

    const int li   = lane & 7;
    const int quad = lane >> 3;
    const int aRow = li + (quad & 1) * 8;
    const int aCol = (quad >> 1) * 8;
    const int bRow = ((lane >> 3) & 1) * 8 + li;

    const uint32_t sAh = (uint32_t)__cvta_generic_to_shared(&Ahs[0][0]);
    const uint32_t sAl = (uint32_t)__cvta_generic_to_shared(&Als[0][0]);
    const uint32_t sBh = (uint32_t)__cvta_generic_to_shared(&Bhs[0][0]);
    const uint32_t sBl = (uint32_t)__cvta_generic_to_shared(&Bls[0][0]);

    float acc[2][4][4];
#pragma unroll
    for (int mt = 0; mt < 2; mt++)
#pragma unroll
        for (int nt = 0; nt < 4; nt++)
#pragma unroll
            for (int i = 0; i < 4; i++) acc[mt][nt][i] = 0.f;

    float4 pa[4], pb[2];
#pragma unroll
    for (int i = 0; i < 4; i++) {
        int f = tid + i * 256;
        int r = f >> 3, kq = f & 7;
        int grow = rowBase + r;
        pa[i] = (grow < M) ? *(const float4*)&A[(size_t)grow * 128 + kq * 4]
                           : make_float4(0.f, 0.f, 0.f, 0.f);
    }
#pragma unroll
    for (int i = 0; i < 2; i++) {
        int f = tid + i * 256;
        int k = f >> 4, cq = f & 15;
        int c0 = colBase + cq * 4;
        pb[i] = (c0 < Ncols) ? *(const float4*)&W[(size_t)k * Ncols + c0]
                             : make_float4(0.f, 0.f, 0.f, 0.f);
    }

    for (int kc = 0; kc < 128; kc += 32) {
        // --- stage to smem ---
#pragma unroll
        for (int i = 0; i < 4; i++) {
            int f = tid + i * 256;
            int r = f >> 3, kq = f & 7;
            if (FULL) {
                __half h0, l0, h1, l1, h2, l2, h3, l3;
                h_split(pa[i].x, h0, l0); h_split(pa[i].y, h1, l1);
                h_split(pa[i].z, h2, l2); h_split(pa[i].w, h3, l3);
                *(uint2*)&Ahs[r][kq * 4] = make_uint2(pack_h2(h0, h1), pack_h2(h2, h3));
                *(uint2*)&Als[r][kq * 4] = make_uint2(pack_h2(l0, l1), pack_h2(l2, l3));
            } else {
                *(uint2*)&Ahs[r][kq * 4] = make_uint2(
                    pack_h2(__float2half_rn(pa[i].x), __float2half_rn(pa[i].y)),
                    pack_h2(__float2half_rn(pa[i].z), __float2half_rn(pa[i].w)));
            }
        }
#pragma unroll
        for (int i = 0; i < 2; i++) {
            int f = tid + i * 256;
            int k = f >> 4, cq = f & 15;
            if (FULL) {
                __half h0, l0, h1, l1, h2, l2, h3, l3;
                h_split(pb[i].x, h0, l0); h_split(pb[i].y, h1, l1);
                h_split(pb[i].z, h2, l2); h_split(pb[i].w, h3, l3);
                *(uint2*)&Bhs[k][cq * 4] = make_uint2(pack_h2(h0, h1), pack_h2(h2, h3));
                *(uint2*)&Bls[k][cq * 4] = make_uint2(pack_h2(l0, l1), pack_h2(l2, l3));
            } else {
                *(uint2*)&Bhs[k][cq * 4] = make_uint2(
                    pack_h2(__float2half_rn(pb[i].x), __float2half_rn(pb[i].y)),
                    pack_h2(__float2half_rn(pb[i].z), __float2half_rn(pb[i].w)));
            }
        }
        __syncthreads();

        int kn = kc + 32;
        if (kn < 128) {
#pragma unroll
            for (int i = 0; i < 4; i++) {
                int f = tid + i * 256;
                int r = f >> 3, kq = f & 7;
                int grow = rowBase + r;
                pa[i] = (grow < M) ? *(const float4*)&A[(size_t)grow * 128 + kn + kq * 4]
                                   : make_float4(0.f, 0.f, 0.f, 0.f);
            }
#pragma unroll
            for (int i = 0; i < 2; i++) {
                int f = tid + i * 256;
                int k = f >> 4, cq = f & 15;
                int c0 = colBase + cq * 4;
                pb[i] = (c0 < Ncols) ? *(const float4*)&W[(size_t)(kn + k) * Ncols + c0]
                                     : make_float4(0.f, 0.f, 0.f, 0.f);
            }
        }

#pragma unroll
        for (int ks = 0; ks < 2; ks++) {
            const int ko = ks * 16;

            uint32_t bh[4][2], bl[4][2];
#pragma unroll
            for (int nt = 0; nt < 4; nt++) {
                int n0 = wn + nt * 8;
                uint32_t boff = (uint32_t)(((ko + bRow) * 72 + n0) * 2);
                ldsm_x2t(bh[nt][0], bh[nt][1], sBh + boff);
                if (FULL) ldsm_x2t(bl[nt][0], bl[nt][1], sBl + boff);
            }

#pragma unroll
            for (int mt = 0; mt < 2; mt++) {
                int r0 = wm + mt * 16;
                uint32_t aoff = (uint32_t)(((r0 + aRow) * 40 + ko + aCol) * 2);
                uint32_t a0, a1, a2, a3;
                ldsm_x4(a0, a1, a2, a3, sAh + aoff);
#pragma unroll
                for (int nt = 0; nt < 4; nt++)
                    mma_f16(acc[mt][nt], a0, a1, a2, a3, bh[nt][0], bh[nt][1]);
                if (FULL) {
                    uint32_t l0, l1, l2, l3;
                    ldsm_x4(l0, l1, l2, l3, sAl + aoff);
#pragma unroll
                    for (int nt = 0; nt < 4; nt++)
                        mma_f16(acc[mt][nt], l0, l1, l2, l3, bh[nt][0], bh[nt][1]);
#pragma unroll
                    for (int nt = 0; nt < 4; nt++)
                        mma_f16(acc[mt][nt], a0, a1, a2, a3, bl[nt][0], bl[nt][1]);
                }
            }
        }
        __syncthreads();
    }

#pragma unroll
    for (int mt = 0; mt < 2; mt++) {
#pragma unroll
        for (int nt = 0; nt < 4; nt++) {
            int col = colBase + wn + nt * 8 + 2 * tg;
            if (col >= Ncols) continue;
            int r0 = rowBase + wm + mt * 16 + g;
            int r1 = r0 + 8;
            if (r0 < M)
                *(__half2*)&C[(size_t)r0 * Ncols + col] =
                    __floats2half2_rn(acc[mt][nt][0], acc[mt][nt][1]);
            if (r1 < M)
                *(__half2*)&C[(size_t)r1 * Ncols + col] =
                    __floats2half2_rn(acc[mt][nt][2], acc[mt][nt][3]);
        }
    }
}

// ---------------- fused CSR gather for F=128 (fp16 input) --------------------
__global__ __launch_bounds__(256) void gather128_kernel(
    const __half* __restrict__ h, float* __restrict__ out,
    const float* __restrict__ bias, int do_relu)
{
    int warp = threadIdx.x >> 5;
    int lane = threadIdx.x & 31;
    int node = blockIdx.x * 8 + warp;
    if (node >= N_NODES) return;

    float dd = g_dis[node];
    float4 acc0, acc1;
    {
        uint2 u = *(const uint2*)(h + (size_t)node * 128 + lane * 4);
        float2 f01 = __half22float2(*(__half2*)&u.x);
        float2 f23 = __half22float2(*(__half2*)&u.y);
        acc0 = make_float4(f01.x * dd, f01.y * dd, f23.x * dd, f23.y * dd);
        acc1 = make_float4(0.f, 0.f, 0.f, 0.f);
    }

    int e   = g_rowptr[node];
    int end = g_rowptr[node + 1];

    for (; e + 3 < end; e += 4) {
        int s0 = g_csrc[e];
        int s1 = g_csrc[e + 1];
        int s2 = g_csrc[e + 2];
        int s3 = g_csrc[e + 3];
        float d0 = g_dis[s0], d1 = g_dis[s1], d2 = g_dis[s2], d3 = g_dis[s3];
        uint2 u0 = *(const uint2*)(h + (size_t)s0 * 128 + lane * 4);
        uint2 u1 = *(const uint2*)(h + (size_t)s1 * 128 + lane * 4);
        uint2 u2 = *(const uint2*)(h + (size_t)s2 * 128 + lane * 4);
        uint2 u3 = *(const uint2*)(h + (size_t)s3 * 128 + lane * 4);
        float2 a01 = __half22float2(*(__half2*)&u0.x), a23 = __half22float2(*(__half2*)&u0.y);
        float2 b01 = __half22float2(*(__half2*)&u1.x), b23 = __half22float2(*(__half2*)&u1.y);
        float2 c01 = __half22float2(*(__half2*)&u2.x), c23 = __half22float2(*(__half2*)&u2.y);
        float2 e01 = __half22float2(*(__half2*)&u3.x), e23 = __half22float2(*(__half2*)&u3.y);
        acc0.x += a01.x * d0 + c01.x * d2;
        acc0.y += a01.y * d0 + c01.y * d2;
        acc0.z += a23.x * d0 + c23.x * d2;
        acc0.w += a23.y * d0 + c23.y * d2;
        acc1.x += b01.x * d1 + e01.x * d3;
        acc1.y += b01.y * d1 + e01.y * d3;
        acc1.z += b23.x * d1 + e23.x * d3;
        acc1.w += b23.y * d1 + e23.y * d3;
    }
    for (; e < end; e++) {
        int s0 = g_csrc[e];
        float d0 = g_dis[s0];
        uint2 u0 = *(const uint2*)(h + (size_t)s0 * 128 + lane * 4);
        float2 a01 = __half22float2(*(__half2*)&u0.x), a23 = __half22float2(*(__half2*)&u0.y);
        acc0.x += a01.x * d0; acc0.y += a01.y * d0; acc0.z += a23.x * d0; acc0.w += a23.y * d0;
    }

    float4 b = *(const float4*)&bias[lane * 4];
    float4 r;
    r.x = (acc0.x + acc1.x) * dd + b.x;
    r.y = (acc0.y + acc1.y) * dd + b.y;
    r.z = (acc0.z + acc1.z) * dd + b.z;
    r.w = (acc0.w + acc1.w) * dd + b.w;
    if (do_relu) {
        r.x = fmaxf(r.x, 0.f); r.y = fmaxf(r.y, 0.f);
        r.z = fmaxf(r.z, 0.f); r.w = fmaxf(r.w, 0.f);
    }
    *(float4*)&out[(size_t)node * 128 + lane * 4] = r;
}

// ------- fused CSR gather (F=40, fp16 in) + bias + log-softmax ---------------
__global__ __launch_bounds__(256) void gather40_softmax_kernel(
    const __half* __restrict__ h, const float* __restrict__ bias,
    float* __restrict__ out)
{
    int warp = threadIdx.x >> 5;
    int lane = threadIdx.x & 31;
    int node = blockIdx.x * 8 + warp;
    if (node >= N_NODES) return;

    const bool act = (lane < 20);
    float dd = g_dis[node];
    float accA = 0.f, accB = 0.f;
    if (act) {
        __half2 v = *(const __half2*)(h + (size_t)node * N_CLS + lane * 2);
        float2 f = __half22float2(v);
        accA = f.x * dd; accB = f.y * dd;
    }

    int e   = g_rowptr[node];
    int end = g_rowptr[node + 1];
    for (; e + 1 < end; e += 2) {
        int s0 = g_csrc[e];
        int s1 = g_csrc[e + 1];
        float d0 = g_dis[s0];
        float d1 = g_dis[s1];
        if (act) {
            float2 f0 = __half22float2(*(const __half2*)(h + (size_t)s0 * N_CLS + lane * 2));
            float2 f1 = __half22float2(*(const __half2*)(h + (size_t)s1 * N_CLS + lane * 2));
            accA += f0.x * d0 + f1.x * d1;
            accB += f0.y * d0 + f1.y * d1;
        }
    }
    if (e < end) {
        int s0 = g_csrc[e];
        float d0 = g_dis[s0];
        if (act) {
            float2 f0 = __half22float2(*(const __half2*)(h + (size_t)s0 * N_CLS + lane * 2));
            accA += f0.x * d0;
            accB += f0.y * d0;
        }
    }

    float a = act ? (accA * dd + bias[lane * 2])     : -INFINITY;
    float b = act ? (accB * dd + bias[lane * 2 + 1]) : -INFINITY;

    float m = fmaxf(a, b);
#pragma unroll
    for (int off = 16; off > 0; off >>= 1)
        m = fmaxf(m, __shfl_xor_sync(0xFFFFFFFFu, m, off));

    float s = act ? (expf(a - m) + expf(b - m)) : 0.f;
#pragma unroll
    for (int off = 16; off > 0; off >>= 1)
        s += __shfl_xor_sync(0xFFFFFFFFu, s, off);

    float lse = m + logf(s);
    if (act) {
        float2 r = make_float2(a - lse, b - lse);
        *(float2*)&out[(size_t)node * N_CLS + lane * 2] = r;
    }
}

// ---------------- launch ------------------------------------------------------
extern "C" void kernel_launch(void* const* d_in, const int* in_sizes, int n_in,
                              void* d_out, int out_size) {
    const float* x  = (const float*)d_in[0];
    const int*   ei = (const int*)d_in[1];      // int32 [2][N_EDGES]
    const float* W1 = (const float*)d_in[2];
    const float* b1 = (const float*)d_in[3];
    const float* W2 = (const float*)d_in[4];
    const float* b2 = (const float*)d_in[5];
    const float* W3 = (const float*)d_in[6];
    const float* b3 = (const float*)d_in[7];
    float* out = (float*)d_out;

    __half* t_ptr;
    float*  x_ptr;
    cudaGetSymbolAddress((void**)&t_ptr, g_t);
    cudaGetSymbolAddress((void**)&x_ptr, g_x);

    static cudaStream_t s2 = nullptr;
    static cudaEvent_t evFork = nullptr, evJoin = nullptr;
    if (s2 == nullptr) {
        cudaStreamCreateWithFlags(&s2, cudaStreamNonBlocking);
        cudaEventCreateWithFlags(&evFork, cudaEventDisableTiming);
        cudaEventCreateWithFlags(&evJoin, cudaEventDisableTiming);
    }

    const int gemmGridX  = (N_NODES + 127) / 128;
    const dim3 gemmGrid128(gemmGridX, 2);   // 128 cols -> 2 n-blocks
    const dim3 gemmGrid40(gemmGridX, 1);    // 40 cols  -> 1 n-block
    const int gatherGrid = (N_NODES + 7) / 8;

    // ---- fork: CSR build on s2 (fast coalesced scan), gemm-1 on main -------
    cudaEventRecord(evFork, 0);
    cudaStreamWaitEvent(s2, evFork, 0);

    zero_deg_kernel<<<(N_NODES + 255) / 256, 256, 0, s2>>>();
    hist_deg_kernel<<<(N_EDGES + 255) / 256, 256, 0, s2>>>(ei);
    scan_p1_kernel<<<SCAN_BLOCKS, 1024, 0, s2>>>();
    scan_p2_kernel<<<1, 128, 0, s2>>>();
    scan_p3_kernel<<<SCAN_BLOCKS, 1024, 0, s2>>>();
    csr_fill_kernel<<<(N_EDGES + 255) / 256, 256, 0, s2>>>(ei);
    cudaEventRecord(evJoin, s2);

    // layer-1 GEMM: 3-term (accurate) — hides under the CSR chain for free
    gemm_f16_kernel<true><<<gemmGrid128, 256>>>(x, W1, t_ptr, N_NODES, 128);

    // ---- join: gather-1 needs both CSR and GEMM-1 ----
    cudaStreamWaitEvent(0, evJoin, 0);
    gather128_kernel<<<gatherGrid, 256>>>(t_ptr, x_ptr, b1, 1);

    // ---- layer 2: pure fp16 GEMM (error budget calibrated) ----
    gemm_f16_kernel<false><<<gemmGrid128, 256>>>(x_ptr, W2, t_ptr, N_NODES, 128);
    gather128_kernel<<<gatherGrid, 256>>>(t_ptr, x_ptr, b2, 1);

    // ---- layer 3 (40 cols): pure fp16 GEMM + fused log-softmax ----
    gemm_f16_kernel<false><<<gemmGrid40, 256>>>(x_ptr, W3, t_ptr, N_NODES, N_CLS);
    gather40_softmax_kernel<<<gatherGrid, 256>>>(t_ptr, b3, out);
}

// round 16
// speedup vs baseline: 1.9851x; 1.0199x over previous
#include <cuda_runtime.h>
#include <cuda_fp16.h>
#include <stdint.h>
#include <math.h>

#define N_NODES 100000
#define N_EDGES 1600000
#define N_CLS   40
#define SCAN_BLOCKS 98   // ceil(100000 / 1024)

// ---------------- scratch (static device arrays; no cudaMalloc) -------------
__device__ __half g_t[(size_t)N_NODES * 128];   // transform output (x @ W), fp16
__device__ __half g_x[(size_t)N_NODES * 128];   // layer activation buffer, fp16
__device__ int    g_deg[N_NODES];
__device__ float  g_dis[N_NODES];               // (deg+1)^{-1/2}
__device__ int    g_rowptr[N_NODES + 1];
__device__ int    g_cursor[N_NODES];
__device__ int    g_csrc[N_EDGES];              // CSR: src ids grouped by dst
__device__ int    g_bsum[128];                  // per-block degree sums
__device__ int    g_boff[128];                  // exclusive block offsets

// ---------------- degree histogram ------------------------------------------
__global__ void zero_deg_kernel() {
    int i = blockIdx.x * blockDim.x + threadIdx.x;
    if (i < N_NODES) g_deg[i] = 0;
}

__global__ void hist_deg_kernel(const int* __restrict__ ei) {
    int e = blockIdx.x * blockDim.x + threadIdx.x;
    if (e < N_EDGES) atomicAdd(&g_deg[ei[N_EDGES + e]], 1);
}

// ---------------- 3-phase coalesced scan -------------------------------------
__global__ __launch_bounds__(1024) void scan_p1_kernel() {
    int i = blockIdx.x * 1024 + threadIdx.x;
    int v = (i < N_NODES) ? g_deg[i] : 0;
    int lane = threadIdx.x & 31, wid = threadIdx.x >> 5;
#pragma unroll
    for (int off = 16; off > 0; off >>= 1)
        v += __shfl_down_sync(0xFFFFFFFFu, v, off);
    __shared__ int ws[32];
    if (lane == 0) ws[wid] = v;
    __syncthreads();
    if (wid == 0) {
        int s = ws[lane];
#pragma unroll
        for (int off = 16; off > 0; off >>= 1)
            s += __shfl_down_sync(0xFFFFFFFFu, s, off);
        if (lane == 0) g_bsum[blockIdx.x] = s;
    }
}

__global__ void scan_p2_kernel() {
    __shared__ int s[SCAN_BLOCKS];
    int t = threadIdx.x;
    if (t < SCAN_BLOCKS) s[t] = g_bsum[t];
    __syncthreads();
    if (t == 0) {
        int run = 0;
        for (int i = 0; i < SCAN_BLOCKS; i++) {
            int v = s[i];
            s[i] = run;
            run += v;
        }
    }
    __syncthreads();
    if (t < SCAN_BLOCKS) g_boff[t] = s[t];
}

__global__ __launch_bounds__(1024) void scan_p3_kernel() {
    int i = blockIdx.x * 1024 + threadIdx.x;
    int lane = threadIdx.x & 31, wid = threadIdx.x >> 5;
    int val = (i < N_NODES) ? g_deg[i] : 0;

    int x = val;
#pragma unroll
    for (int off = 1; off < 32; off <<= 1) {
        int n = __shfl_up_sync(0xFFFFFFFFu, x, off);
        if (lane >= off) x += n;
    }
    __shared__ int ws[32];
    if (lane == 31) ws[wid] = x;
    __syncthreads();
    if (wid == 0) {
        int y = ws[lane];
#pragma unroll
        for (int off = 1; off < 32; off <<= 1) {
            int n = __shfl_up_sync(0xFFFFFFFFu, y, off);
            if (lane >= off) y += n;
        }
        ws[lane] = y;
    }
    __syncthreads();
    int woff = (wid > 0) ? ws[wid - 1] : 0;
    int incl = x + woff;
    int excl = incl - val;
    int base = g_boff[blockIdx.x];

    if (i < N_NODES) {
        int p = base + excl;
        g_rowptr[i] = p;
        g_cursor[i] = p;
        g_dis[i] = rsqrtf((float)(val + 1));
        if (i == N_NODES - 1) g_rowptr[N_NODES] = base + incl;
    }
}

__global__ void csr_fill_kernel(const int* __restrict__ ei) {
    int e = blockIdx.x * blockDim.x + threadIdx.x;
    if (e < N_EDGES) {
        int s = ei[e];
        int d = ei[N_EDGES + e];
        int pos = atomicAdd(&g_cursor[d], 1);
        g_csrc[pos] = s;
    }
}

// ---------------- helpers ----------------------------------------------------
__device__ __forceinline__ void h_split(float x, __half& hi, __half& lo) {
    __half h = __float2half_rn(x);
    hi = h;
    lo = __float2half_rn(x - __half2float(h));
}

__device__ __forceinline__ uint32_t pack_h2(__half a, __half b) {
    __half2 h = __halves2half2(a, b);
    return *(uint32_t*)&h;
}

__device__ __forceinline__ void mma_f16(float* c, uint32_t a0, uint32_t a1,
                                        uint32_t a2, uint32_t a3,
                                        uint32_t b0, uint32_t b1) {
    asm volatile(
        "mma.sync.aligned.m16n8k16.row.col.f32.f16.f16.f32 "
        "{%0,%1,%2,%3}, {%4,%5,%6,%7}, {%8,%9}, {%0,%1,%2,%3};"
        : "+f"(c[0]), "+f"(c[1]), "+f"(c[2]), "+f"(c[3])
        : "r"(a0), "r"(a1), "r"(a2), "r"(a3), "r"(b0), "r"(b1));
}

__device__ __forceinline__ void ldsm_x4(uint32_t& r0, uint32_t& r1,
                                        uint32_t& r2, uint32_t& r3, uint32_t addr) {
    asm volatile("ldmatrix.sync.aligned.m8n8.x4.shared.b16 {%0,%1,%2,%3}, [%4];"
                 : "=r"(r0), "=r"(r1), "=r"(r2), "=r"(r3) : "r"(addr));
}

__device__ __forceinline__ void ldsm_x2t(uint32_t& r0, uint32_t& r1, uint32_t addr) {
    asm volatile("ldmatrix.sync.aligned.m8n8.x2.trans.shared.b16 {%0,%1}, [%2];"
                 : "=r"(r0), "=r"(r1) : "r"(addr));
}

// ---------------- 3-term fp16 GEMM (A fp32) — layer 1 ------------------------
__global__ __launch_bounds__(256, 2) void gemm_f16_full_kernel(
    const float* __restrict__ A, const float* __restrict__ W,
    __half* __restrict__ C, int M, int Ncols)
{
    __shared__ __half Ahs[128][40];
    __shared__ __half Als[128][40];
    __shared__ __half Bhs[32][72];
    __shared__ __half Bls[32][72];

    const int tid  = threadIdx.x;
    const int warp = tid >> 5;
    const int lane = tid & 31;
    const int g    = lane >> 2;
    const int tg   = lane & 3;
    const int wm   = (warp >> 1) * 32;
    const int wn   = (warp & 1) * 32;
    const int rowBase = blockIdx.x * 128;
    const int colBase = blockIdx.y * 64;

    const int li   = lane & 7;
    const int quad = lane >> 3;
    const int aRow = li + (quad & 1) * 8;
    const int aCol = (quad >> 1) * 8;
    const int bRow = ((lane >> 3) & 1) * 8 + li;

    const uint32_t sAh = (uint32_t)__cvta_generic_to_shared(&Ahs[0][0]);
    const uint32_t sAl = (uint32_t)__cvta_generic_to_shared(&Als[0][0]);
    const uint32_t sBh = (uint32_t)__cvta_generic_to_shared(&Bhs[0][0]);
    const uint32_t sBl = (uint32_t)__cvta_generic_to_shared(&Bls[0][0]);

    float acc[2][4][4];
#pragma unroll
    for (int mt = 0; mt < 2; mt++)
#pragma unroll
        for (int nt = 0; nt < 4; nt++)
#pragma unroll
            for (int i = 0; i < 4; i++) acc[mt][nt][i] = 0.f;

    float4 pa[4], pb[2];
#pragma unroll
    for (int i = 0; i < 4; i++) {
        int f = tid + i * 256;
        int r = f >> 3, kq = f & 7;
        int grow = rowBase + r;
        pa[i] = (grow < M) ? *(const float4*)&A[(size_t)grow * 128 + kq * 4]
                           : make_float4(0.f, 0.f, 0.f, 0.f);
    }
#pragma unroll
    for (int i = 0; i < 2; i++) {
        int f = tid + i * 256;
        int k = f >> 4, cq = f & 15;
        int c0 = colBase + cq * 4;
        pb[i] = (c0 < Ncols) ? *(const float4*)&W[(size_t)k * Ncols + c0]
                             : make_float4(0.f, 0.f, 0.f, 0.f);
    }

    for (int kc = 0; kc < 128; kc += 32) {
#pragma unroll
        for (int i = 0; i < 4; i++) {
            int f = tid + i * 256;
            int r = f >> 3, kq = f & 7;
            __half h0, l0, h1, l1, h2, l2, h3, l3;
            h_split(pa[i].x, h0, l0); h_split(pa[i].y, h1, l1);
            h_split(pa[i].z, h2, l2); h_split(pa[i].w, h3, l3);
            *(uint2*)&Ahs[r][kq * 4] = make_uint2(pack_h2(h0, h1), pack_h2(h2, h3));
            *(uint2*)&Als[r][kq * 4] = make_uint2(pack_h2(l0, l1), pack_h2(l2, l3));
        }
#pragma unroll
        for (int i = 0; i < 2; i++) {
            int f = tid + i * 256;
            int k = f >> 4, cq = f & 15;
            __half h0, l0, h1, l1, h2, l2, h3, l3;
            h_split(pb[i].x, h0, l0); h_split(pb[i].y, h1, l1);
            h_split(pb[i].z, h2, l2); h_split(pb[i].w, h3, l3);
            *(uint2*)&Bhs[k][cq * 4] = make_uint2(pack_h2(h0, h1), pack_h2(h2, h3));
            *(uint2*)&Bls[k][cq * 4] = make_uint2(pack_h2(l0, l1), pack_h2(l2, l3));
        }
        __syncthreads();

        int kn = kc + 32;
        if (kn < 128) {
#pragma unroll
            for (int i = 0; i < 4; i++) {
                int f = tid + i * 256;
                int r = f >> 3, kq = f & 7;
                int grow = rowBase + r;
                pa[i] = (grow < M) ? *(const float4*)&A[(size_t)grow * 128 + kn + kq * 4]
                                   : make_float4(0.f, 0.f, 0.f, 0.f);
            }
#pragma unroll
            for (int i = 0; i < 2; i++) {
                int f = tid + i * 256;
                int k = f >> 4, cq = f & 15;
                int c0 = colBase + cq * 4;
                pb[i] = (c0 < Ncols) ? *(const float4*)&W[(size_t)(kn + k) * Ncols + c0]
                                     : make_float4(0.f, 0.f, 0.f, 0.f);
            }
        }

#pragma unroll
        for (int ks = 0; ks < 2; ks++) {
            const int ko = ks * 16;
            uint32_t bh[4][2], bl[4][2];
#pragma unroll
            for (int nt = 0; nt < 4; nt++) {
                int n0 = wn + nt * 8;
                uint32_t boff = (uint32_t)(((ko + bRow) * 72 + n0) * 2);
                ldsm_x2t(bh[nt][0], bh[nt][1], sBh + boff);
                ldsm_x2t(bl[nt][0], bl[nt][1], sBl + boff);
            }
#pragma unroll
            for (int mt = 0; mt < 2; mt++) {
                int r0 = wm + mt * 16;
                uint32_t aoff = (uint32_t)(((r0 + aRow) * 40 + ko + aCol) * 2);
                uint32_t a0, a1, a2, a3, l0, l1, l2, l3;
                ldsm_x4(a0, a1, a2, a3, sAh + aoff);
                ldsm_x4(l0, l1, l2, l3, sAl + aoff);
#pragma unroll
                for (int nt = 0; nt < 4; nt++)
                    mma_f16(acc[mt][nt], a0, a1, a2, a3, bh[nt][0], bh[nt][1]);
#pragma unroll
                for (int nt = 0; nt < 4; nt++)
                    mma_f16(acc[mt][nt], l0, l1, l2, l3, bh[nt][0], bh[nt][1]);
#pragma unroll
                for (int nt = 0; nt < 4; nt++)
                    mma_f16(acc[mt][nt], a0, a1, a2, a3, bl[nt][0], bl[nt][1]);
            }
        }
        __syncthreads();
    }

#pragma unroll
    for (int mt = 0; mt < 2; mt++) {
#pragma unroll
        for (int nt = 0; nt < 4; nt++) {
            int col = colBase + wn + nt * 8 + 2 * tg;
            if (col >= Ncols) continue;
            int r0 = rowBase + wm + mt * 16 + g;
            int r1 = r0 + 8;
            if (r0 < M)
                *(__half2*)&C[(size_t)r0 * Ncols + col] =
                    __floats2half2_rn(acc[mt][nt][0], acc[mt][nt][1]);
            if (r1 < M)
                *(__half2*)&C[(size_t)r1 * Ncols + col] =
                    __floats2half2_rn(acc[mt][nt][2], acc[mt][nt][3]);
        }
    }
}

// ---------------- fast fp16 GEMM (A fp16) — layers 2/3 -----------------------
__global__ __launch_bounds__(256, 2) void gemm_f16_fast_kernel(
    const __half* __restrict__ A, const float* __restrict__ W,
    __half* __restrict__ C, int M, int Ncols)
{
    __shared__ __half Ahs[128][40];
    __shared__ __half Bhs[32][72];

    const int tid  = threadIdx.x;
    const int warp = tid >> 5;
    const int lane = tid & 31;
    const int g    = lane >> 2;
    const int tg   = lane & 3;
    const int wm   = (warp >> 1) * 32;
    const int wn   = (warp & 1) * 32;
    const int rowBase = blockIdx.x * 128;
    const int colBase = blockIdx.y * 64;

    const int li   = lane & 7;
    const int quad = lane >> 3;
    const int aRow = li + (quad & 1) * 8;
    const int aCol = (quad >> 1) * 8;
    const int bRow = ((lane >> 3) & 1) * 8 + li;

    const uint32_t sAh = (uint32_t)__cvta_generic_to_shared(&Ahs[0][0]);
    const uint32_t sBh = (uint32_t)__cvta_generic_to_shared(&Bhs[0][0]);

    float acc[2][4][4];
#pragma unroll
    for (int mt = 0; mt < 2; mt++)
#pragma unroll
        for (int nt = 0; nt < 4; nt++)
#pragma unroll
            for (int i = 0; i < 4; i++) acc[mt][nt][i] = 0.f;

    // A: 128x32 halves = 1024 uint2-loads of 4 halves, 4/thread.
    uint2 pa[4];
    float4 pb[2];
#pragma unroll
    for (int i = 0; i < 4; i++) {
        int f = tid + i * 256;
        int r = f >> 3, kq = f & 7;
        int grow = rowBase + r;
        pa[i] = (grow < M) ? *(const uint2*)&A[(size_t)grow * 128 + kq * 4]
                           : make_uint2(0u, 0u);
    }
#pragma unroll
    for (int i = 0; i < 2; i++) {
        int f = tid + i * 256;
        int k = f >> 4, cq = f & 15;
        int c0 = colBase + cq * 4;
        pb[i] = (c0 < Ncols) ? *(const float4*)&W[(size_t)k * Ncols + c0]
                             : make_float4(0.f, 0.f, 0.f, 0.f);
    }

    for (int kc = 0; kc < 128; kc += 32) {
#pragma unroll
        for (int i = 0; i < 4; i++) {
            int f = tid + i * 256;
            int r = f >> 3, kq = f & 7;
            *(uint2*)&Ahs[r][kq * 4] = pa[i];
        }
#pragma unroll
        for (int i = 0; i < 2; i++) {
            int f = tid + i * 256;
            int k = f >> 4, cq = f & 15;
            *(uint2*)&Bhs[k][cq * 4] = make_uint2(
                pack_h2(__float2half_rn(pb[i].x), __float2half_rn(pb[i].y)),
                pack_h2(__float2half_rn(pb[i].z), __float2half_rn(pb[i].w)));
        }
        __syncthreads();

        int kn = kc + 32;
        if (kn < 128) {
#pragma unroll
            for (int i = 0; i < 4; i++) {
                int f = tid + i * 256;
                int r = f >> 3, kq = f & 7;
                int grow = rowBase + r;
                pa[i] = (grow < M) ? *(const uint2*)&A[(size_t)grow * 128 + kn + kq * 4]
                                   : make_uint2(0u, 0u);
            }
#pragma unroll
            for (int i = 0; i < 2; i++) {
                int f = tid + i * 256;
                int k = f >> 4, cq = f & 15;
                int c0 = colBase + cq * 4;
                pb[i] = (c0 < Ncols) ? *(const float4*)&W[(size_t)(kn + k) * Ncols + c0]
                                     : make_float4(0.f, 0.f, 0.f, 0.f);
            }
        }

#pragma unroll
        for (int ks = 0; ks < 2; ks++) {
            const int ko = ks * 16;
            uint32_t bh[4][2];
#pragma unroll
            for (int nt = 0; nt < 4; nt++) {
                int n0 = wn + nt * 8;
                uint32_t boff = (uint32_t)(((ko + bRow) * 72 + n0) * 2);
                ldsm_x2t(bh[nt][0], bh[nt][1], sBh + boff);
            }
#pragma unroll
            for (int mt = 0; mt < 2; mt++) {
                int r0 = wm + mt * 16;
                uint32_t aoff = (uint32_t)(((r0 + aRow) * 40 + ko + aCol) * 2);
                uint32_t a0, a1, a2, a3;
                ldsm_x4(a0, a1, a2, a3, sAh + aoff);
#pragma unroll
                for (int nt = 0; nt < 4; nt++)
                    mma_f16(acc[mt][nt], a0, a1, a2, a3, bh[nt][0], bh[nt][1]);
            }
        }
        __syncthreads();
    }

#pragma unroll
    for (int mt = 0; mt < 2; mt++) {
#pragma unroll
        for (int nt = 0; nt < 4; nt++) {
            int col = colBase + wn + nt * 8 + 2 * tg;
            if (col >= Ncols) continue;
            int r0 = rowBase + wm + mt * 16 + g;
            int r1 = r0 + 8;
            if (r0 < M)
                *(__half2*)&C[(size_t)r0 * Ncols + col] =
                    __floats2half2_rn(acc[mt][nt][0], acc[mt][nt][1]);
            if (r1 < M)
                *(__half2*)&C[(size_t)r1 * Ncols + col] =
                    __floats2half2_rn(acc[mt][nt][2], acc[mt][nt][3]);
        }
    }
}

// ---------------- fused CSR gather F=128 (fp16 in, fp16 out) -----------------
__global__ __launch_bounds__(512) void gather128_kernel(
    const __half* __restrict__ h, __half* __restrict__ out,
    const float* __restrict__ bias, int do_relu)
{
    int warp = threadIdx.x >> 5;
    int lane = threadIdx.x & 31;
    int node = blockIdx.x * 16 + warp;
    if (node >= N_NODES) return;

    float dd = g_dis[node];
    float4 acc0, acc1;
    {
        uint2 u = *(const uint2*)(h + (size_t)node * 128 + lane * 4);
        float2 f01 = __half22float2(*(__half2*)&u.x);
        float2 f23 = __half22float2(*(__half2*)&u.y);
        acc0 = make_float4(f01.x * dd, f01.y * dd, f23.x * dd, f23.y * dd);
        acc1 = make_float4(0.f, 0.f, 0.f, 0.f);
    }

    int e   = g_rowptr[node];
    int end = g_rowptr[node + 1];

    for (; e + 3 < end; e += 4) {
        int s0 = g_csrc[e];
        int s1 = g_csrc[e + 1];
        int s2 = g_csrc[e + 2];
        int s3 = g_csrc[e + 3];
        float d0 = g_dis[s0], d1 = g_dis[s1], d2 = g_dis[s2], d3 = g_dis[s3];
        uint2 u0 = *(const uint2*)(h + (size_t)s0 * 128 + lane * 4);
        uint2 u1 = *(const uint2*)(h + (size_t)s1 * 128 + lane * 4);
        uint2 u2 = *(const uint2*)(h + (size_t)s2 * 128 + lane * 4);
        uint2 u3 = *(const uint2*)(h + (size_t)s3 * 128 + lane * 4);
        float2 a01 = __half22float2(*(__half2*)&u0.x), a23 = __half22float2(*(__half2*)&u0.y);
        float2 b01 = __half22float2(*(__half2*)&u1.x), b23 = __half22float2(*(__half2*)&u1.y);
        float2 c01 = __half22float2(*(__half2*)&u2.x), c23 = __half22float2(*(__half2*)&u2.y);
        float2 e01 = __half22float2(*(__half2*)&u3.x), e23 = __half22float2(*(__half2*)&u3.y);
        acc0.x += a01.x * d0 + c01.x * d2;
        acc0.y += a01.y * d0 + c01.y * d2;
        acc0.z += a23.x * d0 + c23.x * d2;
        acc0.w += a23.y * d0 + c23.y * d2;
        acc1.x += b01.x * d1 + e01.x * d3;
        acc1.y += b01.y * d1 + e01.y * d3;
        acc1.z += b23.x * d1 + e23.x * d3;
        acc1.w += b23.y * d1 + e23.y * d3;
    }
    for (; e < end; e++) {
        int s0 = g_csrc[e];
        float d0 = g_dis[s0];
        uint2 u0 = *(const uint2*)(h + (size_t)s0 * 128 + lane * 4);
        float2 a01 = __half22float2(*(__half2*)&u0.x), a23 = __half22float2(*(__half2*)&u0.y);
        acc0.x += a01.x * d0; acc0.y += a01.y * d0; acc0.z += a23.x * d0; acc0.w += a23.y * d0;
    }

    float4 b = *(const float4*)&bias[lane * 4];
    float rx = (acc0.x + acc1.x) * dd + b.x;
    float ry = (acc0.y + acc1.y) * dd + b.y;
    float rz = (acc0.z + acc1.z) * dd + b.z;
    float rw = (acc0.w + acc1.w) * dd + b.w;
    if (do_relu) {
        rx = fmaxf(rx, 0.f); ry = fmaxf(ry, 0.f);
        rz = fmaxf(rz, 0.f); rw = fmaxf(rw, 0.f);
    }
    uint2 o = make_uint2(pack_h2(__float2half_rn(rx), __float2half_rn(ry)),
                         pack_h2(__float2half_rn(rz), __float2half_rn(rw)));
    *(uint2*)(out + (size_t)node * 128 + lane * 4) = o;
}

// ------- fused CSR gather (F=40, fp16 in) + bias + log-softmax ---------------
__global__ __launch_bounds__(512) void gather40_softmax_kernel(
    const __half* __restrict__ h, const float* __restrict__ bias,
    float* __restrict__ out)
{
    int warp = threadIdx.x >> 5;
    int lane = threadIdx.x & 31;
    int node = blockIdx.x * 16 + warp;
    if (node >= N_NODES) return;

    const bool act = (lane < 20);
    float dd = g_dis[node];
    float accA = 0.f, accB = 0.f;
    if (act) {
        __half2 v = *(const __half2*)(h + (size_t)node * N_CLS + lane * 2);
        float2 f = __half22float2(v);
        accA = f.x * dd; accB = f.y * dd;
    }

    int e   = g_rowptr[node];
    int end = g_rowptr[node + 1];
    for (; e + 1 < end; e += 2) {
        int s0 = g_csrc[e];
        int s1 = g_csrc[e + 1];
        float d0 = g_dis[s0];
        float d1 = g_dis[s1];
        if (act) {
            float2 f0 = __half22float2(*(const __half2*)(h + (size_t)s0 * N_CLS + lane * 2));
            float2 f1 = __half22float2(*(const __half2*)(h + (size_t)s1 * N_CLS + lane * 2));
            accA += f0.x * d0 + f1.x * d1;
            accB += f0.y * d0 + f1.y * d1;
        }
    }
    if (e < end) {
        int s0 = g_csrc[e];
        float d0 = g_dis[s0];
        if (act) {
            float2 f0 = __half22float2(*(const __half2*)(h + (size_t)s0 * N_CLS + lane * 2));
            accA += f0.x * d0;
            accB += f0.y * d0;
        }
    }

    float a = act ? (accA * dd + bias[lane * 2])     : -INFINITY;
    float b = act ? (accB * dd + bias[lane * 2 + 1]) : -INFINITY;

    float m = fmaxf(a, b);
#pragma unroll
    for (int off = 16; off > 0; off >>= 1)
        m = fmaxf(m, __shfl_xor_sync(0xFFFFFFFFu, m, off));

    float s = act ? (expf(a - m) + expf(b - m)) : 0.f;
#pragma unroll
    for (int off = 16; off > 0; off >>= 1)
        s += __shfl_xor_sync(0xFFFFFFFFu, s, off);

    float lse = m + logf(s);
    if (act) {
        float2 r = make_float2(a - lse, b - lse);
        *(float2*)&out[(size_t)node * N_CLS + lane * 2] = r;
    }
}

// ---------------- launch ------------------------------------------------------
extern "C" void kernel_launch(void* const* d_in, const int* in_sizes, int n_in,
                              void* d_out, int out_size) {
    const float* x  = (const float*)d_in[0];
    const int*   ei = (const int*)d_in[1];      // int32 [2][N_EDGES]
    const float* W1 = (const float*)d_in[2];
    const float* b1 = (const float*)d_in[3];
    const float* W2 = (const float*)d_in[4];
    const float* b2 = (const float*)d_in[5];
    const float* W3 = (const float*)d_in[6];
    const float* b3 = (const float*)d_in[7];
    float* out = (float*)d_out;

    __half* t_ptr;
    __half* x_ptr;
    cudaGetSymbolAddress((void**)&t_ptr, g_t);
    cudaGetSymbolAddress((void**)&x_ptr, g_x);

    static cudaStream_t s2 = nullptr;
    static cudaEvent_t evFork = nullptr, evJoin = nullptr;
    if (s2 == nullptr) {
        cudaStreamCreateWithFlags(&s2, cudaStreamNonBlocking);
        cudaEventCreateWithFlags(&evFork, cudaEventDisableTiming);
        cudaEventCreateWithFlags(&evJoin, cudaEventDisableTiming);
    }

    const int gemmGridX  = (N_NODES + 127) / 128;
    const dim3 gemmGrid128(gemmGridX, 2);   // 128 cols -> 2 n-blocks
    const dim3 gemmGrid40(gemmGridX, 1);    // 40 cols  -> 1 n-block
    const int gatherGrid = (N_NODES + 15) / 16;

    // ---- fork: CSR build on s2 (fast coalesced scan), gemm-1 on main -------
    cudaEventRecord(evFork, 0);
    cudaStreamWaitEvent(s2, evFork, 0);

    zero_deg_kernel<<<(N_NODES + 255) / 256, 256, 0, s2>>>();
    hist_deg_kernel<<<(N_EDGES + 255) / 256, 256, 0, s2>>>(ei);
    scan_p1_kernel<<<SCAN_BLOCKS, 1024, 0, s2>>>();
    scan_p2_kernel<<<1, 128, 0, s2>>>();
    scan_p3_kernel<<<SCAN_BLOCKS, 1024, 0, s2>>>();
    csr_fill_kernel<<<(N_EDGES + 255) / 256, 256, 0, s2>>>(ei);
    cudaEventRecord(evJoin, s2);

    // layer-1 GEMM: 3-term (accurate) — hides under the CSR chain for free
    gemm_f16_full_kernel<<<gemmGrid128, 256>>>(x, W1, t_ptr, N_NODES, 128);

    // ---- join: gather-1 needs both CSR and GEMM-1 ----
    cudaStreamWaitEvent(0, evJoin, 0);
    gather128_kernel<<<gatherGrid, 512>>>(t_ptr, x_ptr, b1, 1);

    // ---- layer 2: fast fp16 GEMM (A fp16) ----
    gemm_f16_fast_kernel<<<gemmGrid128, 256>>>(x_ptr, W2, t_ptr, N_NODES, 128);
    gather128_kernel<<<gatherGrid, 512>>>(t_ptr, x_ptr, b2, 1);

    // ---- layer 3 (40 cols): fast fp16 GEMM + fused log-softmax ----
    gemm_f16_fast_kernel<<<gemmGrid40, 256>>>(x_ptr, W3, t_ptr, N_NODES, N_CLS);
    gather40_softmax_kernel<<<gatherGrid, 512>>>(t_ptr, b3, out);
}